// round 7
// baseline (speedup 1.0000x reference)
#include <cuda_runtime.h>

#define EPS_F 1e-5f
#define BDIM 128
#define CDIM 32
#define NA 12
#define NB 12
#define PDIM 8192

#define TPB 256
#define TILE_P 256   // points per block

// Folded conv+bn weights, computed by prologue kernel each launch.
__device__ float g_wfold[CDIM * CDIM];
__device__ float g_bfold[CDIM];

// ---------------------------------------------------------------------------
// Prologue: fold bn1 + conv + bn2 into W', bias'
//   z[o] = sum_c (W[o][c]*s1[c]*s2[o]) * agg[c] + (s2[o]*sum_c W[o][c]*t1[c] + t2[o])
// ---------------------------------------------------------------------------
__global__ void fold_kernel(const float* __restrict__ w,
                            const float* __restrict__ g1, const float* __restrict__ b1,
                            const float* __restrict__ m1, const float* __restrict__ v1,
                            const float* __restrict__ g2, const float* __restrict__ b2,
                            const float* __restrict__ m2, const float* __restrict__ v2) {
    __shared__ float s1[CDIM], t1[CDIM], s2[CDIM], t2[CDIM];
    int t = threadIdx.x;
    if (t < CDIM) {
        float sc1 = g1[t] * rsqrtf(v1[t] + EPS_F);
        s1[t] = sc1;
        t1[t] = b1[t] - m1[t] * sc1;
        float sc2 = g2[t] * rsqrtf(v2[t] + EPS_F);
        s2[t] = sc2;
        t2[t] = b2[t] - m2[t] * sc2;
    }
    __syncthreads();
    if (t < CDIM * CDIM) {
        int o = t >> 5;
        int c = t & 31;
        g_wfold[t] = w[t] * s1[c] * s2[o];
    }
    if (t < CDIM) {
        int o = t;
        float s = 0.f;
        #pragma unroll
        for (int c = 0; c < CDIM; c++) s += w[o * CDIM + c] * t1[c];
        g_bfold[o] = s * s2[o] + t2[o];
    }
}

// ---------------------------------------------------------------------------
// Packed f32x2 helpers (sm_103a FFMA2 path — ptxas never emits this from C++)
// ---------------------------------------------------------------------------
__device__ __forceinline__ unsigned long long pack2(float lo, float hi) {
    unsigned long long r;
    asm("mov.b64 %0, {%1, %2};" : "=l"(r) : "f"(lo), "f"(hi));
    return r;
}
__device__ __forceinline__ void unpack2(unsigned long long v, float& lo, float& hi) {
    asm("mov.b64 {%0, %1}, %2;" : "=f"(lo), "=f"(hi) : "l"(v));
}
__device__ __forceinline__ unsigned long long fma2(unsigned long long a,
                                                   unsigned long long b,
                                                   unsigned long long c) {
    unsigned long long d;
    asm("fma.rn.f32x2 %0, %1, %2, %3;" : "=l"(d) : "l"(a), "l"(b), "l"(c));
    return d;
}

// ---------------------------------------------------------------------------
// Main fused kernel, two-phase:
//   Phase 1: each of 256 threads gather-max-aggregates ONE point into a
//            shared agg tile aggS[32 c][256 n].
//   Phase 2: register-tiled GEMM C[o][n] = W'[o][c] * agg[c][n] + b'.
//            Thread tile 4 o x 8 n (two strided float4 groups).
//            FFMA2 lanes = (n, n+1): weights pre-duplicated in shared
//            (warp-uniform loads -> broadcast), agg pairs come straight
//            out of shared in lane order with zero packing movs.
// grid = (PDIM/TILE_P, BDIM); block = 256.
// ---------------------------------------------------------------------------
__global__ __launch_bounds__(TPB, 3) void feynnet_kernel(
    const float* __restrict__ feat_a, const float* __restrict__ feat_b,
    const int* __restrict__ assign_a, const int* __restrict__ assign_b,
    float* __restrict__ out) {
    __shared__ float fa[CDIM * NA];                   // 1.5 KB
    __shared__ float fb[CDIM * NB];                   // 1.5 KB
    __shared__ unsigned long long w2t[CDIM * CDIM];   // [c][o] dup pairs, 8 KB
    __shared__ unsigned long long bias2[CDIM];        // dup pairs
    __shared__ float aggS[CDIM * TILE_P];             // [c][n], 32 KB

    const int t = threadIdx.x;
    const int b = blockIdx.y;
    const int ptile = blockIdx.x * TILE_P;

    // ---- Phase 0: stage feats, transposed-dup weights, dup bias ----
    for (int i = t; i < CDIM * NA; i += TPB) fa[i] = feat_a[b * CDIM * NA + i];
    for (int i = t; i < CDIM * NB; i += TPB) fb[i] = feat_b[b * CDIM * NB + i];
    for (int i = t; i < CDIM * CDIM; i += TPB) {
        int c = i >> 5;
        int o = i & 31;
        float w = g_wfold[o * CDIM + c];
        w2t[i] = pack2(w, w);           // w2t[c*32 + o] = (w[o][c], w[o][c])
    }
    if (t < CDIM) {
        float bb = g_bfold[t];
        bias2[t] = pack2(bb, bb);
    }
    __syncthreads();

    // ---- Phase 1: gather + max-aggregate one point per thread ----
    // Conflict-free: for fixed c the 12 candidate words span 12 distinct
    // banks; duplicated indices across lanes hit the multicast path.
    {
        const int p = ptile + t;
        const int2 aa = *reinterpret_cast<const int2*>(assign_a + 2 * p);
        const int2 ab = *reinterpret_cast<const int2*>(assign_b + 2 * p);
        #pragma unroll
        for (int c = 0; c < CDIM; c++) {
            const float* ra = fa + c * NA;
            const float* rb = fb + c * NB;
            float v = fmaxf(fmaxf(ra[aa.x], ra[aa.y]),
                            fmaxf(rb[ab.x], rb[ab.y]));
            aggS[c * TILE_P + t] = v;
        }
    }
    __syncthreads();

    // ---- Phase 2: register-tiled GEMM ----
    const int og = t >> 5;        // 0..7 -> o block of 4 (warp-uniform)
    const int ng = t & 31;        // 0..31 -> point groups
    const int o0 = og * 4;

    // acc[o][j]: j=0,1 -> point group0 (points 4ng..4ng+3)
    //            j=2,3 -> point group1 (points 128+4ng..+3)
    unsigned long long acc[4][4];
    #pragma unroll
    for (int o = 0; o < 4; o++) {
        unsigned long long bb = bias2[o0 + o];
        acc[o][0] = bb; acc[o][1] = bb; acc[o][2] = bb; acc[o][3] = bb;
    }

    const ulonglong2* agg64 = reinterpret_cast<const ulonglong2*>(aggS);
    // row stride in ulonglong2: TILE_P/4 = 64 per c

    #pragma unroll
    for (int c = 0; c < CDIM; c++) {
        const ulonglong2 w01 = *reinterpret_cast<const ulonglong2*>(&w2t[c * CDIM + o0]);
        const ulonglong2 w23 = *reinterpret_cast<const ulonglong2*>(&w2t[c * CDIM + o0 + 2]);
        const ulonglong2 a0 = agg64[c * (TILE_P / 4) + ng];        // pairs (4ng,4ng+1),(4ng+2,4ng+3)
        const ulonglong2 a1 = agg64[c * (TILE_P / 4) + 32 + ng];   // +128 points

        acc[0][0] = fma2(w01.x, a0.x, acc[0][0]);
        acc[0][1] = fma2(w01.x, a0.y, acc[0][1]);
        acc[0][2] = fma2(w01.x, a1.x, acc[0][2]);
        acc[0][3] = fma2(w01.x, a1.y, acc[0][3]);

        acc[1][0] = fma2(w01.y, a0.x, acc[1][0]);
        acc[1][1] = fma2(w01.y, a0.y, acc[1][1]);
        acc[1][2] = fma2(w01.y, a1.x, acc[1][2]);
        acc[1][3] = fma2(w01.y, a1.y, acc[1][3]);

        acc[2][0] = fma2(w23.x, a0.x, acc[2][0]);
        acc[2][1] = fma2(w23.x, a0.y, acc[2][1]);
        acc[2][2] = fma2(w23.x, a1.x, acc[2][2]);
        acc[2][3] = fma2(w23.x, a1.y, acc[2][3]);

        acc[3][0] = fma2(w23.y, a0.x, acc[3][0]);
        acc[3][1] = fma2(w23.y, a0.y, acc[3][1]);
        acc[3][2] = fma2(w23.y, a1.x, acc[3][2]);
        acc[3][3] = fma2(w23.y, a1.y, acc[3][3]);
    }

    // ---- Epilogue: relu + coalesced float4 stores ----
    float* outb = out + (size_t)b * CDIM * PDIM + ptile;
    #pragma unroll
    for (int o = 0; o < 4; o++) {
        float* rowp = outb + (size_t)(o0 + o) * PDIM;
        float x0, x1, x2, x3;

        unpack2(acc[o][0], x0, x1);
        unpack2(acc[o][1], x2, x3);
        *reinterpret_cast<float4*>(rowp + 4 * ng) =
            make_float4(fmaxf(x0, 0.f), fmaxf(x1, 0.f),
                        fmaxf(x2, 0.f), fmaxf(x3, 0.f));

        unpack2(acc[o][2], x0, x1);
        unpack2(acc[o][3], x2, x3);
        *reinterpret_cast<float4*>(rowp + 128 + 4 * ng) =
            make_float4(fmaxf(x0, 0.f), fmaxf(x1, 0.f),
                        fmaxf(x2, 0.f), fmaxf(x3, 0.f));
    }
}

// ---------------------------------------------------------------------------
// Launch
// ---------------------------------------------------------------------------
extern "C" void kernel_launch(void* const* d_in, const int* in_sizes, int n_in,
                              void* d_out, int out_size) {
    const float* feat_a = (const float*)d_in[0];
    const float* feat_b = (const float*)d_in[1];
    const int* assign_a = (const int*)d_in[2];
    const int* assign_b = (const int*)d_in[3];
    const float* bn1_gamma = (const float*)d_in[4];
    const float* bn1_beta = (const float*)d_in[5];
    const float* bn1_mean = (const float*)d_in[6];
    const float* bn1_var = (const float*)d_in[7];
    const float* conv_w = (const float*)d_in[8];
    const float* bn2_gamma = (const float*)d_in[9];
    const float* bn2_beta = (const float*)d_in[10];
    const float* bn2_mean = (const float*)d_in[11];
    const float* bn2_var = (const float*)d_in[12];
    float* out = (float*)d_out;

    fold_kernel<<<1, CDIM * CDIM>>>(conv_w, bn1_gamma, bn1_beta, bn1_mean, bn1_var,
                                    bn2_gamma, bn2_beta, bn2_mean, bn2_var);

    dim3 grid(PDIM / TILE_P, BDIM);
    feynnet_kernel<<<grid, TPB>>>(feat_a, feat_b, assign_a, assign_b, out);
}